// round 14
// baseline (speedup 1.0000x reference)
#include <cuda_runtime.h>
#include <cuda_bf16.h>
#include <math.h>

#define BATCH  2
#define NTOK   962
#define DIM    384
#define NH     6
#define DH     64
#define NLAYER 12
#define ROWS   (BATCH*NTOK)          // 1924
#define QKVD   (3*DIM)               // 1152
#define HIDD   (4*DIM)               // 1536
#define FEAT_SIZE (ROWS*DIM)         // 738816
#define SSTR   1024                  // padded score stride (fp32)
#define PSTR   512                   // padded prob stride in pairs
#define NZ     (BATCH*NH)            // 12 attention batches

typedef unsigned long long u64;
typedef unsigned int u32;
typedef long long ll;

// ---------------- scratch (static device globals; no allocation) -------------
__device__ float g_x  [ROWS*DIM];                 // fp32 residual stream
__device__ u32   g_lnh[ROWS*(DIM/2)];             // LN out split-bf16 (pairs)
__device__ u32   g_lnl[ROWS*(DIM/2)];
__device__ u32   g_qh [ROWS*(QKVD/2)];            // qkv split-bf16 (pairs)
__device__ u32   g_ql [ROWS*(QKVD/2)];
__device__ float g_sc [NZ*NTOK*SSTR];             // scores fp32 padded (47MB)
__device__ u32   g_ph [NZ*NTOK*PSTR];             // probs split-bf16 padded
__device__ u32   g_pl [NZ*NTOK*PSTR];
__device__ u32   g_ch [ROWS*(DIM/2)];             // ctx split-bf16
__device__ u32   g_cl [ROWS*(DIM/2)];
__device__ u32   g_hh [ROWS*(HIDD/2)];            // hid split-bf16
__device__ u32   g_hl [ROWS*(HIDD/2)];
__device__ u32   g_wh [294912];                   // weight colpair (reused)
__device__ u32   g_wl [294912];

// ---------------- helpers ----------------------------------------------------
__device__ __forceinline__ void split2(float x, float y, u32& hi, u32& lo) {
    __nv_bfloat162 h = __floats2bfloat162_rn(x, y);
    float rx = x - __bfloat162float(h.x);
    float ry = y - __bfloat162float(h.y);
    __nv_bfloat162 l = __floats2bfloat162_rn(rx, ry);
    hi = *(u32*)&h; lo = *(u32*)&l;
}
__device__ __forceinline__ void mma16816(float c[4],
    u32 a0, u32 a1, u32 a2, u32 a3, u32 b0, u32 b1)
{
    asm volatile(
        "mma.sync.aligned.m16n8k16.row.col.f32.bf16.bf16.f32 "
        "{%0,%1,%2,%3}, {%4,%5,%6,%7}, {%8,%9}, {%0,%1,%2,%3};"
        : "+f"(c[0]), "+f"(c[1]), "+f"(c[2]), "+f"(c[3])
        : "r"(a0), "r"(a1), "r"(a2), "r"(a3), "r"(b0), "r"(b1));
}
// smem pair layout: per 8-pair group, column order [0,4,1,5,2,6,3,7]
#define ASTR 24
__device__ __forceinline__ int pcol1(int p) {
    return (p >> 3) * 8 + ((p & 7 & 3) * 2 + ((p & 7) >> 2));
}
__device__ __forceinline__ void pcol(int p0, int& c0, int& c1) {
    c0 = pcol1(p0); c1 = pcol1(p0 + 1);
}

// ---------------- compute core shared by all mma kernels ---------------------
#define MMA_COMPUTE(Ahs, Als, Bhs, Bls)                                         \
    _Pragma("unroll")                                                           \
    for (int s = 0; s < 2; s++) {                                               \
        const int co = s * 8 + 2 * tg;                                          \
        uint2 AH0[2], AH1[2], AL0[2], AL1[2];                                   \
        _Pragma("unroll")                                                       \
        for (int mt = 0; mt < 2; mt++) {                                        \
            int rb = (mw * 32 + mt * 16 + g) * ASTR + co;                       \
            AH0[mt] = *(const uint2*)&Ahs[rb];                                  \
            AH1[mt] = *(const uint2*)&Ahs[rb + 8 * ASTR];                       \
            AL0[mt] = *(const uint2*)&Als[rb];                                  \
            AL1[mt] = *(const uint2*)&Als[rb + 8 * ASTR];                       \
        }                                                                       \
        uint2 BHf[4], BLf[4];                                                   \
        _Pragma("unroll")                                                       \
        for (int nt = 0; nt < 4; nt++) {                                        \
            int rb = (nw * 32 + nt * 8 + g) * ASTR + co;                        \
            BHf[nt] = *(const uint2*)&Bhs[rb];                                  \
            BLf[nt] = *(const uint2*)&Bls[rb];                                  \
        }                                                                       \
        _Pragma("unroll")                                                       \
        for (int mt = 0; mt < 2; mt++) {                                        \
            _Pragma("unroll")                                                   \
            for (int nt = 0; nt < 4; nt++) {                                    \
                mma16816(acc[mt][nt], AH0[mt].x, AH1[mt].x, AH0[mt].y, AH1[mt].y,\
                         BHf[nt].x, BHf[nt].y);                                 \
                mma16816(acc[mt][nt], AH0[mt].x, AH1[mt].x, AH0[mt].y, AH1[mt].y,\
                         BLf[nt].x, BLf[nt].y);                                 \
                mma16816(acc[mt][nt], AL0[mt].x, AL1[mt].x, AL0[mt].y, AL1[mt].y,\
                         BHf[nt].x, BHf[nt].y);                                 \
            }                                                                   \
        }                                                                       \
    }

// ---------------- dense GEMM (pre-split operands) ----------------------------
// C = act(A @ B + bias) [+res].  A: rowK pairs [M x ldaP], B: colpair [K/2 x N].
// K%32==0, N%64==0. CTA 256 thr = 8 warps (4Mx2N); tile 128x64; K-chunks 32.
template<bool DOGELU, bool HASRES, bool WB16>
__global__ __launch_bounds__(256) void mma_dense(
    const u32* __restrict__ Ahi, const u32* __restrict__ Alo,
    const u32* __restrict__ Bhi, const u32* __restrict__ Blo,
    const float* __restrict__ bias, const float* __restrict__ res,
    float* __restrict__ C, u32* __restrict__ Chi, u32* __restrict__ Clo,
    int M, int N, int K)
{
    __shared__ __align__(16) u32 sAh[128 * ASTR];
    __shared__ __align__(16) u32 sAl[128 * ASTR];
    __shared__ __align__(16) u32 sBh[64 * ASTR];
    __shared__ __align__(16) u32 sBl[64 * ASTR];

    const int ldaP = K >> 1, ldcP = N >> 1;
    const int t = threadIdx.x;
    const int lane = t & 31, wid = t >> 5;
    const int g = lane >> 2, tg = lane & 3;
    const int mw = wid & 3, nw = wid >> 2;
    const int row0 = blockIdx.y * 128;
    const int n0 = blockIdx.x * 64;

    float acc[2][4][4];
    #pragma unroll
    for (int i = 0; i < 2; i++)
        #pragma unroll
        for (int j = 0; j < 4; j++)
            #pragma unroll
            for (int k = 0; k < 4; k++) acc[i][j][k] = 0.f;

    uint2 AhS[4], AlS[4], BhS[2], BlS[2];
    const int nC = K >> 5;

    auto LOADG = [&](int c) {
        int kbP = c << 4;
        #pragma unroll
        for (int i = 0; i < 4; i++) {
            int id = t + (i << 8);
            int m = id >> 3, p2 = (id & 7) << 1;
            int gm = row0 + m;
            if (gm < M) {
                AhS[i] = *(const uint2*)&Ahi[(ll)gm * ldaP + kbP + p2];
                AlS[i] = *(const uint2*)&Alo[(ll)gm * ldaP + kbP + p2];
            } else { AhS[i] = make_uint2(0u,0u); AlS[i] = make_uint2(0u,0u); }
        }
        #pragma unroll
        for (int i = 0; i < 2; i++) {
            int id = t + (i << 8);
            int kp = id >> 5, n2 = id & 31;
            ll off = (ll)(kbP + kp) * N + n0 + 2 * n2;
            BhS[i] = *(const uint2*)&Bhi[off];
            BlS[i] = *(const uint2*)&Blo[off];
        }
    };
    auto STORES = [&]() {
        #pragma unroll
        for (int i = 0; i < 4; i++) {
            int id = t + (i << 8);
            int m = id >> 3, p2 = (id & 7) << 1;
            int c0, c1; pcol(p2, c0, c1);
            sAh[m * ASTR + c0] = AhS[i].x; sAh[m * ASTR + c1] = AhS[i].y;
            sAl[m * ASTR + c0] = AlS[i].x; sAl[m * ASTR + c1] = AlS[i].y;
        }
        #pragma unroll
        for (int i = 0; i < 2; i++) {
            int id = t + (i << 8);
            int kp = id >> 5, n2 = id & 31;
            int cc = pcol1(kp);
            sBh[(2 * n2) * ASTR + cc] = BhS[i].x;
            sBh[(2 * n2 + 1) * ASTR + cc] = BhS[i].y;
            sBl[(2 * n2) * ASTR + cc] = BlS[i].x;
            sBl[(2 * n2 + 1) * ASTR + cc] = BlS[i].y;
        }
    };

    LOADG(0); STORES();
    __syncthreads();

    for (int c = 0; c < nC; c++) {
        const bool more = (c + 1 < nC);
        if (more) LOADG(c + 1);
        MMA_COMPUTE(sAh, sAl, sBh, sBl);
        __syncthreads();
        if (more) { STORES(); __syncthreads(); }
    }

    #pragma unroll
    for (int mt = 0; mt < 2; mt++) {
        #pragma unroll
        for (int half = 0; half < 2; half++) {
            int gm = row0 + mw * 32 + mt * 16 + half * 8 + g;
            if (gm >= M) continue;
            #pragma unroll
            for (int nt = 0; nt < 4; nt++) {
                int gn = n0 + nw * 32 + nt * 8 + 2 * tg;
                float v0 = acc[mt][nt][half * 2 + 0] + bias[gn];
                float v1 = acc[mt][nt][half * 2 + 1] + bias[gn + 1];
                if (DOGELU) {
                    v0 = 0.5f * v0 * (1.f + erff(v0 * 0.70710678118654752440f));
                    v1 = 0.5f * v1 * (1.f + erff(v1 * 0.70710678118654752440f));
                }
                if (HASRES) {
                    v0 += res[(ll)gm * N + gn];
                    v1 += res[(ll)gm * N + gn + 1];
                }
                if (WB16) {
                    u32 h, l; split2(v0, v1, h, l);
                    Chi[(ll)gm * ldcP + (gn >> 1)] = h;
                    Clo[(ll)gm * ldcP + (gn >> 1)] = l;
                } else {
                    *(float2*)&C[(ll)gm * N + gn] = make_float2(v0, v1);
                }
            }
        }
    }
}

// ---------------- batched attention GEMM (pre-split operands) ----------------
// TRANSB=true : C(fp32,ldc) = alpha * A @ B^T  (QK^T; B rowK, rows<Bvalid)
// TRANSB=false: Cbf16        = A @ B           (PV; B rowK along K=tokens,
//                              repacked to col-pairs with PRMT at fill)
template<bool TRANSB, bool WB16>
__global__ __launch_bounds__(256) void tmma(
    const u32* __restrict__ Ahi, const u32* __restrict__ Alo, int ldaP,
    const u32* __restrict__ Bhi, const u32* __restrict__ Blo, int ldbP,
    float* __restrict__ C, int ldc, u32* __restrict__ Chi, u32* __restrict__ Clo,
    int ldcP, int M, int K, int Hn,
    ll sAb, ll sAh_, ll sBb, ll sBh_, ll sCb, ll sCh_,
    float alpha, int Bvalid)
{
    __shared__ __align__(16) u32 sAh[128 * ASTR];
    __shared__ __align__(16) u32 sAl[128 * ASTR];
    __shared__ __align__(16) u32 sBh[64 * ASTR];
    __shared__ __align__(16) u32 sBl[64 * ASTR];

    const int zb = blockIdx.z / Hn;
    const int zh = blockIdx.z % Hn;
    Ahi += zb * sAb + zh * sAh_;  Alo += zb * sAb + zh * sAh_;
    Bhi += zb * sBb + zh * sBh_;  Blo += zb * sBb + zh * sBh_;
    if (WB16) { Chi += zb * sCb + zh * sCh_; Clo += zb * sCb + zh * sCh_; }
    else      { C   += zb * sCb + zh * sCh_; }

    const int t = threadIdx.x;
    const int lane = t & 31, wid = t >> 5;
    const int g = lane >> 2, tg = lane & 3;
    const int mw = wid & 3, nw = wid >> 2;
    const int row0 = blockIdx.y * 128;
    const int n0 = blockIdx.x * 64;

    float acc[2][4][4];
    #pragma unroll
    for (int i = 0; i < 2; i++)
        #pragma unroll
        for (int j = 0; j < 4; j++)
            #pragma unroll
            for (int k = 0; k < 4; k++) acc[i][j][k] = 0.f;

    uint2 AhS[4], AlS[4];
    u32 Bh0[2], Bh1[2], Bl0[2], Bl1[2];   // PV path staging
    uint2 BhT[2], BlT[2];                 // QK^T path staging
    const int nC = K >> 5;

    auto LOADG = [&](int c) {
        int kbP = c << 4;
        #pragma unroll
        for (int i = 0; i < 4; i++) {
            int id = t + (i << 8);
            int m = id >> 3, p2 = (id & 7) << 1;
            int gm = row0 + m;
            if (gm < M) {
                AhS[i] = *(const uint2*)&Ahi[(ll)gm * ldaP + kbP + p2];
                AlS[i] = *(const uint2*)&Alo[(ll)gm * ldaP + kbP + p2];
            } else { AhS[i] = make_uint2(0u,0u); AlS[i] = make_uint2(0u,0u); }
        }
        if (TRANSB) {
            #pragma unroll
            for (int i = 0; i < 2; i++) {
                int id = t + (i << 8);
                int n = id >> 3, p2 = (id & 7) << 1;
                int gn = n0 + n;
                if (gn < Bvalid) {
                    BhT[i] = *(const uint2*)&Bhi[(ll)gn * ldbP + kbP + p2];
                    BlT[i] = *(const uint2*)&Blo[(ll)gn * ldbP + kbP + p2];
                } else { BhT[i] = make_uint2(0u,0u); BlT[i] = make_uint2(0u,0u); }
            }
        } else {
            int kb = c << 5;
            #pragma unroll
            for (int i = 0; i < 2; i++) {
                int id = t + (i << 8);
                int kp = id >> 5, n2 = id & 31;
                int tk0 = kb + 2 * kp, tk1 = tk0 + 1;
                u32 rh0 = (tk0 < Bvalid) ? Bhi[(ll)tk0 * ldbP + n2] : 0u;
                u32 rh1 = (tk1 < Bvalid) ? Bhi[(ll)tk1 * ldbP + n2] : 0u;
                u32 rl0 = (tk0 < Bvalid) ? Blo[(ll)tk0 * ldbP + n2] : 0u;
                u32 rl1 = (tk1 < Bvalid) ? Blo[(ll)tk1 * ldbP + n2] : 0u;
                Bh0[i] = __byte_perm(rh0, rh1, 0x5410);   // col 2n2
                Bh1[i] = __byte_perm(rh0, rh1, 0x7632);   // col 2n2+1
                Bl0[i] = __byte_perm(rl0, rl1, 0x5410);
                Bl1[i] = __byte_perm(rl0, rl1, 0x7632);
            }
        }
    };
    auto STORES = [&]() {
        #pragma unroll
        for (int i = 0; i < 4; i++) {
            int id = t + (i << 8);
            int m = id >> 3, p2 = (id & 7) << 1;
            int c0, c1; pcol(p2, c0, c1);
            sAh[m * ASTR + c0] = AhS[i].x; sAh[m * ASTR + c1] = AhS[i].y;
            sAl[m * ASTR + c0] = AlS[i].x; sAl[m * ASTR + c1] = AlS[i].y;
        }
        if (TRANSB) {
            #pragma unroll
            for (int i = 0; i < 2; i++) {
                int id = t + (i << 8);
                int n = id >> 3, p2 = (id & 7) << 1;
                int c0, c1; pcol(p2, c0, c1);
                sBh[n * ASTR + c0] = BhT[i].x; sBh[n * ASTR + c1] = BhT[i].y;
                sBl[n * ASTR + c0] = BlT[i].x; sBl[n * ASTR + c1] = BlT[i].y;
            }
        } else {
            #pragma unroll
            for (int i = 0; i < 2; i++) {
                int id = t + (i << 8);
                int kp = id >> 5, n2 = id & 31;
                int cc = pcol1(kp);
                sBh[(2 * n2) * ASTR + cc] = Bh0[i];
                sBh[(2 * n2 + 1) * ASTR + cc] = Bh1[i];
                sBl[(2 * n2) * ASTR + cc] = Bl0[i];
                sBl[(2 * n2 + 1) * ASTR + cc] = Bl1[i];
            }
        }
    };

    LOADG(0); STORES();
    __syncthreads();

    for (int c = 0; c < nC; c++) {
        const bool more = (c + 1 < nC);
        if (more) LOADG(c + 1);
        MMA_COMPUTE(sAh, sAl, sBh, sBl);
        __syncthreads();
        if (more) { STORES(); __syncthreads(); }
    }

    #pragma unroll
    for (int mt = 0; mt < 2; mt++) {
        #pragma unroll
        for (int half = 0; half < 2; half++) {
            int gm = row0 + mw * 32 + mt * 16 + half * 8 + g;
            if (gm >= M) continue;
            #pragma unroll
            for (int nt = 0; nt < 4; nt++) {
                int gn = n0 + nw * 32 + nt * 8 + 2 * tg;
                float v0 = acc[mt][nt][half * 2 + 0] * alpha;
                float v1 = acc[mt][nt][half * 2 + 1] * alpha;
                if (WB16) {
                    u32 h, l; split2(v0, v1, h, l);
                    Chi[(ll)gm * ldcP + (gn >> 1)] = h;
                    Clo[(ll)gm * ldcP + (gn >> 1)] = l;
                } else {
                    *(float2*)&C[(ll)gm * ldc + gn] = make_float2(v0, v1);
                }
            }
        }
    }
}

// ---------------- weight converter: fp32 [K x N] -> colpair hi/lo ------------
__global__ void conv_w(const float* __restrict__ w, u32* __restrict__ hi,
                       u32* __restrict__ lo, int KK, int NN)
{
    int idx = blockIdx.x * 256 + threadIdx.x;
    int tot = (KK >> 1) * NN;
    if (idx >= tot) return;
    int kp = idx / NN, n = idx - kp * NN;
    float a = w[(ll)(2 * kp) * NN + n];
    float b = w[(ll)(2 * kp + 1) * NN + n];
    u32 h, l; split2(a, b, h, l);
    hi[idx] = h; lo[idx] = l;
}

// ---------------- layernorm -> split-bf16 pairs ------------------------------
__global__ __launch_bounds__(192) void ln_bf16(
    const float* __restrict__ x, const float* __restrict__ gw,
    const float* __restrict__ bw, u32* __restrict__ oh, u32* __restrict__ ol)
{
    __shared__ float sh[6];
    ll row = blockIdx.x;
    int t = threadIdx.x;
    float2 v = ((const float2*)(x + row * DIM))[t];
    float s = v.x + v.y;
    #pragma unroll
    for (int o = 16; o; o >>= 1) s += __shfl_xor_sync(0xffffffffu, s, o);
    if ((t & 31) == 0) sh[t >> 5] = s;
    __syncthreads();
    float mean = (sh[0]+sh[1]+sh[2]+sh[3]+sh[4]+sh[5]) * (1.f / DIM);
    __syncthreads();
    float dx = v.x - mean, dy = v.y - mean;
    float q = dx * dx + dy * dy;
    #pragma unroll
    for (int o = 16; o; o >>= 1) q += __shfl_xor_sync(0xffffffffu, q, o);
    if ((t & 31) == 0) sh[t >> 5] = q;
    __syncthreads();
    float var = (sh[0]+sh[1]+sh[2]+sh[3]+sh[4]+sh[5]) * (1.f / DIM);
    float r = rsqrtf(var + 1e-6f);
    float2 gg = ((const float2*)gw)[t], bb = ((const float2*)bw)[t];
    float o0 = dx * r * gg.x + bb.x;
    float o1 = dy * r * gg.y + bb.y;
    u32 h, l; split2(o0, o1, h, l);
    oh[row * (DIM/2) + t] = h;
    ol[row * (DIM/2) + t] = l;
}

// ---------------- plain layernorm (final feats, fp32) ------------------------
__global__ __launch_bounds__(128) void ln_k(
    const float* __restrict__ x, const float* __restrict__ g,
    const float* __restrict__ b, float* __restrict__ o)
{
    __shared__ float sh[4];
    ll row = blockIdx.x;
    const float* xr = x + row * DIM;
    float* orow = o + row * DIM;
    int t = threadIdx.x;
    float v0 = xr[t], v1 = xr[t + 128], v2 = xr[t + 256];
    float s = v0 + v1 + v2;
    #pragma unroll
    for (int ofs = 16; ofs; ofs >>= 1) s += __shfl_xor_sync(0xffffffffu, s, ofs);
    if ((t & 31) == 0) sh[t >> 5] = s;
    __syncthreads();
    float mean = (sh[0] + sh[1] + sh[2] + sh[3]) * (1.f / DIM);
    __syncthreads();
    float d0 = v0 - mean, d1 = v1 - mean, d2 = v2 - mean;
    float q = d0*d0 + d1*d1 + d2*d2;
    #pragma unroll
    for (int ofs = 16; ofs; ofs >>= 1) q += __shfl_xor_sync(0xffffffffu, q, ofs);
    if ((t & 31) == 0) sh[t >> 5] = q;
    __syncthreads();
    float var = (sh[0] + sh[1] + sh[2] + sh[3]) * (1.f / DIM);
    float r = rsqrtf(var + 1e-6f);
    orow[t]       = d0 * r * g[t]       + b[t];
    orow[t + 128] = d1 * r * g[t + 128] + b[t + 128];
    orow[t + 256] = d2 * r * g[t + 256] + b[t + 256];
}

// ---------------- softmax + mask (e>=0.1) + renorm -> split-bf16 probs -------
// max(e)=exp(0)=1 exactly, so p>=0.1*max(p) <=> e>=0.1.  Pads (pair>=481) = 0.
__global__ __launch_bounds__(256) void softmax_k(
    const float* __restrict__ S, u32* __restrict__ Ph, u32* __restrict__ Pl,
    float* __restrict__ Pc)
{
    __shared__ float sh[8];
    ll row = blockIdx.x;
    const float* sr = S + row * SSTR;
    int t = threadIdx.x;

    float2 v[2];
    float mx = -3.4e38f;
    #pragma unroll
    for (int i = 0; i < 2; i++) {
        int p = t + i * 256;
        v[i] = (p < 481) ? ((const float2*)sr)[p] : make_float2(-3.4e38f, -3.4e38f);
        mx = fmaxf(mx, fmaxf(v[i].x, v[i].y));
    }
    #pragma unroll
    for (int o = 16; o; o >>= 1) mx = fmaxf(mx, __shfl_xor_sync(0xffffffffu, mx, o));
    if ((t & 31) == 0) sh[t >> 5] = mx;
    __syncthreads();
    float smax = sh[0];
    #pragma unroll
    for (int i = 1; i < 8; i++) smax = fmaxf(smax, sh[i]);
    __syncthreads();

    float sum = 0.f;
    #pragma unroll
    for (int i = 0; i < 2; i++) {
        int p = t + i * 256;
        float e0 = (p < 481) ? __expf(v[i].x - smax) : 0.f;
        float e1 = (p < 481) ? __expf(v[i].y - smax) : 0.f;
        v[i].x = (e0 >= 0.1f) ? e0 : 0.f;
        v[i].y = (e1 >= 0.1f) ? e1 : 0.f;
        sum += v[i].x + v[i].y;
    }
    #pragma unroll
    for (int o = 16; o; o >>= 1) sum += __shfl_xor_sync(0xffffffffu, sum, o);
    if ((t & 31) == 0) sh[t >> 5] = sum;
    __syncthreads();
    float E = sh[0]+sh[1]+sh[2]+sh[3]+sh[4]+sh[5]+sh[6]+sh[7];
    float inv = 1.0f / E;

    #pragma unroll
    for (int i = 0; i < 2; i++) {
        int p = t + i * 256;
        float o0 = v[i].x * inv, o1 = v[i].y * inv;
        u32 h = 0, l = 0;
        if (p < 481) split2(o0, o1, h, l);
        Ph[row * PSTR + p] = h;
        Pl[row * PSTR + p] = l;
        if (Pc && p < 481)
            ((float2*)(Pc + row * NTOK))[p] = make_float2(o0, o1);
    }
}

__global__ void copy_k(const float* __restrict__ a, float* __restrict__ o, int n)
{
    int i = blockIdx.x * 256 + threadIdx.x;
    if (i < n) o[i] = a[i];
}

// -----------------------------------------------------------------------------
extern "C" void kernel_launch(void* const* d_in, const int* in_sizes, int n_in,
                              void* d_out, int out_size)
{
    const float* x_in   = (const float*)d_in[0];
    const float* w_qkv  = (const float*)d_in[1];
    const float* b_qkv  = (const float*)d_in[2];
    const float* w_proj = (const float*)d_in[3];
    const float* b_proj = (const float*)d_in[4];
    const float* ln1g   = (const float*)d_in[5];
    const float* ln1b   = (const float*)d_in[6];
    const float* ln2g   = (const float*)d_in[7];
    const float* ln2b   = (const float*)d_in[8];
    const float* w_fc1  = (const float*)d_in[9];
    const float* b_fc1  = (const float*)d_in[10];
    const float* w_fc2  = (const float*)d_in[11];
    const float* b_fc2  = (const float*)d_in[12];
    const float* lnfg   = (const float*)d_in[13];
    const float* lnfb   = (const float*)d_in[14];

    float* out_feat = (float*)d_out;
    float* out_attn = out_feat + FEAT_SIZE;

    float *x_, *sc_;
    u32 *lnh_, *lnl_, *qh_, *ql_, *ph_, *pl_, *ch_, *cl_, *hh_, *hl_, *wh_, *wl_;
    cudaGetSymbolAddress((void**)&x_,   g_x);
    cudaGetSymbolAddress((void**)&sc_,  g_sc);
    cudaGetSymbolAddress((void**)&lnh_, g_lnh); cudaGetSymbolAddress((void**)&lnl_, g_lnl);
    cudaGetSymbolAddress((void**)&qh_,  g_qh);  cudaGetSymbolAddress((void**)&ql_,  g_ql);
    cudaGetSymbolAddress((void**)&ph_,  g_ph);  cudaGetSymbolAddress((void**)&pl_,  g_pl);
    cudaGetSymbolAddress((void**)&ch_,  g_ch);  cudaGetSymbolAddress((void**)&cl_,  g_cl);
    cudaGetSymbolAddress((void**)&hh_,  g_hh);  cudaGetSymbolAddress((void**)&hl_,  g_hl);
    cudaGetSymbolAddress((void**)&wh_,  g_wh);  cudaGetSymbolAddress((void**)&wl_,  g_wl);

    copy_k<<<(FEAT_SIZE + 255) / 256, 256>>>(x_in, x_, FEAT_SIZE);

    const int mTc = (ROWS + 127) / 128;       // 16 dense M-tiles
    const int yAt = (NTOK + 127) / 128;       // 8 attention M-tiles
    const ll qkvP = (ll)NTOK * (QKVD / 2);    // per-batch qkv pair stride

    for (int l = 0; l < NLAYER; l++) {
        // LN1 -> split bf16
        ln_bf16<<<ROWS, 192>>>(x_, ln1g + l * DIM, ln1b + l * DIM, lnh_, lnl_);

        // qkv: conv weights + gemm -> split bf16 qkv
        conv_w<<<(DIM/2*QKVD + 255)/256, 256>>>(w_qkv + (ll)l*DIM*QKVD, wh_, wl_, DIM, QKVD);
        mma_dense<false, false, true><<<dim3(QKVD/64, mTc), 256>>>(
            lnh_, lnl_, wh_, wl_, b_qkv + l*QKVD, nullptr,
            nullptr, qh_, ql_, ROWS, QKVD, DIM);

        // scores = 0.125 * Q @ K^T  (fp32 padded ldc=1024)
        tmma<true, false><<<dim3(SSTR/64, yAt, NZ), 256>>>(
            qh_, ql_, QKVD/2, qh_ + DIM/2, ql_ + DIM/2, QKVD/2,
            sc_, SSTR, nullptr, nullptr, 0,
            NTOK, DH, NH,
            qkvP, DH/2, qkvP, DH/2,
            (ll)NH*NTOK*SSTR, (ll)NTOK*SSTR,
            0.125f, NTOK);

        // softmax+mask+renorm -> split-bf16 probs (+compact fp32 last layer)
        float* pc = (l == NLAYER - 1) ? out_attn : nullptr;
        softmax_k<<<NZ * NTOK, 256>>>(sc_, ph_, pl_, pc);

        // ctx = P @ V -> split bf16 ctx
        tmma<false, true><<<dim3(1, yAt, NZ), 256>>>(
            ph_, pl_, PSTR, qh_ + 2*(DIM/2), ql_ + 2*(DIM/2), QKVD/2,
            nullptr, 0, ch_, cl_, DIM/2,
            NTOK, SSTR, NH,
            (ll)NH*NTOK*PSTR, (ll)NTOK*PSTR, qkvP, DH/2,
            (ll)NTOK*(DIM/2), DH/2,
            1.0f, NTOK);

        // x += ctx @ w_proj + b_proj  (fp32 out)
        conv_w<<<(DIM/2*DIM + 255)/256, 256>>>(w_proj + (ll)l*DIM*DIM, wh_, wl_, DIM, DIM);
        mma_dense<false, true, false><<<dim3(DIM/64, mTc), 256>>>(
            ch_, cl_, wh_, wl_, b_proj + l*DIM, x_,
            x_, nullptr, nullptr, ROWS, DIM, DIM);

        // LN2 -> split bf16
        ln_bf16<<<ROWS, 192>>>(x_, ln2g + l * DIM, ln2b + l * DIM, lnh_, lnl_);

        // hid = gelu(ln2 @ w_fc1 + b) -> split bf16
        conv_w<<<(DIM/2*HIDD + 255)/256, 256>>>(w_fc1 + (ll)l*DIM*HIDD, wh_, wl_, DIM, HIDD);
        mma_dense<true, false, true><<<dim3(HIDD/64, mTc), 256>>>(
            lnh_, lnl_, wh_, wl_, b_fc1 + l*HIDD, nullptr,
            nullptr, hh_, hl_, ROWS, HIDD, DIM);

        // x += hid @ w_fc2 + b  (fp32 out)
        conv_w<<<(HIDD/2*DIM + 255)/256, 256>>>(w_fc2 + (ll)l*HIDD*DIM, wh_, wl_, HIDD, DIM);
        mma_dense<false, true, false><<<dim3(DIM/64, mTc), 256>>>(
            hh_, hl_, wh_, wl_, b_fc2 + l*DIM, x_,
            x_, nullptr, nullptr, ROWS, DIM, HIDD);
    }

    // final LN -> feats
    ln_k<<<ROWS, 128>>>(x_, lnfg, lnfb, out_feat);
}

// round 16
// speedup vs baseline: 1.2165x; 1.2165x over previous
#include <cuda_runtime.h>
#include <cuda_bf16.h>
#include <math.h>

#define BATCH  2
#define NTOK   962
#define DIM    384
#define NH     6
#define DH     64
#define NLAYER 12
#define ROWS   (BATCH*NTOK)          // 1924
#define QKVD   (3*DIM)               // 1152
#define HIDD   (4*DIM)               // 1536
#define FEAT_SIZE (ROWS*DIM)         // 738816
#define SSTR   1024                  // padded row stride for scores/probs
#define NZ     (BATCH*NH)            // 12 attention batches

typedef unsigned long long u64;
typedef unsigned int u32;
typedef long long ll;

// ---------------- scratch (static device globals; no allocation) -------------
__device__ float g_x  [ROWS*DIM];
__device__ float g_ln [ROWS*DIM];
__device__ float g_qkv[ROWS*QKVD];
__device__ float g_attn [NZ*NTOK*SSTR];   // padded scores (47 MB)
__device__ float g_attnp[NZ*NTOK*SSTR];   // padded probs  (47 MB)
__device__ float g_ctx[ROWS*DIM];
__device__ float g_hid[ROWS*HIDD];
__device__ float g_part[4*ROWS*DIM];      // split-K partials (11.8 MB)

// ---------------- bf16 split helpers -----------------------------------------
__device__ __forceinline__ void split2(float x, float y, u32& hi, u32& lo) {
    __nv_bfloat162 h = __floats2bfloat162_rn(x, y);
    float rx = x - __bfloat162float(h.x);
    float ry = y - __bfloat162float(h.y);
    __nv_bfloat162 l = __floats2bfloat162_rn(rx, ry);
    hi = *(u32*)&h; lo = *(u32*)&l;
}
__device__ __forceinline__ void mma16816(float c[4],
    u32 a0, u32 a1, u32 a2, u32 a3, u32 b0, u32 b1)
{
    asm volatile(
        "mma.sync.aligned.m16n8k16.row.col.f32.bf16.bf16.f32 "
        "{%0,%1,%2,%3}, {%4,%5,%6,%7}, {%8,%9}, {%0,%1,%2,%3};"
        : "+f"(c[0]), "+f"(c[1]), "+f"(c[2]), "+f"(c[3])
        : "r"(a0), "r"(a1), "r"(a2), "r"(a3), "r"(b0), "r"(b1));
}
#define ASTR 24
__device__ __forceinline__ int pcol1(int p) {
    return (p >> 3) * 8 + (((p & 7) & 3) * 2 + ((p & 7) >> 2));
}
__device__ __forceinline__ void pcol(int p0, int& c0, int& c1) {
    c0 = pcol1(p0); c1 = pcol1(p0 + 1);
}

#define MMA_COMPUTE()                                                           \
    _Pragma("unroll")                                                           \
    for (int s = 0; s < 2; s++) {                                               \
        const int co = s * 8 + 2 * tg;                                          \
        uint2 AH0[2], AH1[2], AL0[2], AL1[2];                                   \
        _Pragma("unroll")                                                       \
        for (int mt = 0; mt < 2; mt++) {                                        \
            int rb = (mw * 32 + mt * 16 + g) * ASTR + co;                       \
            AH0[mt] = *(const uint2*)&Ah[rb];                                   \
            AH1[mt] = *(const uint2*)&Ah[rb + 8 * ASTR];                        \
            AL0[mt] = *(const uint2*)&Al[rb];                                   \
            AL1[mt] = *(const uint2*)&Al[rb + 8 * ASTR];                        \
        }                                                                       \
        uint2 BHf[4], BLf[4];                                                   \
        _Pragma("unroll")                                                       \
        for (int nt = 0; nt < 4; nt++) {                                        \
            int rb = (nw * 32 + nt * 8 + g) * ASTR + co;                        \
            BHf[nt] = *(const uint2*)&Bh[rb];                                   \
            BLf[nt] = *(const uint2*)&Bl[rb];                                   \
        }                                                                       \
        _Pragma("unroll")                                                       \
        for (int mt = 0; mt < 2; mt++) {                                        \
            _Pragma("unroll")                                                   \
            for (int nt = 0; nt < 4; nt++) {                                    \
                mma16816(acc[mt][nt], AH0[mt].x, AH1[mt].x, AH0[mt].y, AH1[mt].y,\
                         BHf[nt].x, BHf[nt].y);                                 \
                mma16816(acc[mt][nt], AH0[mt].x, AH1[mt].x, AH0[mt].y, AH1[mt].y,\
                         BLf[nt].x, BLf[nt].y);                                 \
                mma16816(acc[mt][nt], AL0[mt].x, AL1[mt].x, AL0[mt].y, AL1[mt].y,\
                         BHf[nt].x, BHf[nt].y);                                 \
            }                                                                   \
        }                                                                       \
    }

// ---------------- dense HMMA GEMM (fp32 in, convert in-loop) -----------------
// PARTIAL=false: C = act(A@B + bias) [+res], gridDim.z must be 1.
// PARTIAL=true : split-K; CTA z handles K cols [z*K, z*K+K) of Kfull; writes
//                raw partial sums to C + z*M*N (bias/res applied by reducer).
// A row-major lda=Kfull, B row-major ldb=N.  K%32==0, N%64==0.
template<bool DOGELU, bool HASRES, bool PARTIAL>
__global__ __launch_bounds__(256) void mma_gemm(
    const float* __restrict__ A, const float* __restrict__ B,
    const float* __restrict__ bias, const float* __restrict__ res,
    float* __restrict__ C, int M, int N, int K, int Kfull)
{
    __shared__ __align__(16) u32 Ah[128 * ASTR];
    __shared__ __align__(16) u32 Al[128 * ASTR];
    __shared__ __align__(16) u32 Bh[64 * ASTR];
    __shared__ __align__(16) u32 Bl[64 * ASTR];

    const int zs = blockIdx.z;
    A += zs * K;                      // column offset within rows (lda = Kfull)
    B += (ll)zs * K * N;

    const int t = threadIdx.x;
    const int lane = t & 31, wid = t >> 5;
    const int g = lane >> 2, tg = lane & 3;
    const int mw = wid & 3, nw = wid >> 2;
    const int row0 = blockIdx.y * 128;
    const int n0 = blockIdx.x * 64;

    float acc[2][4][4];
    #pragma unroll
    for (int i = 0; i < 2; i++)
        #pragma unroll
        for (int j = 0; j < 4; j++)
            #pragma unroll
            for (int k = 0; k < 4; k++) acc[i][j][k] = 0.f;

    float4 Ar[4];
    float2 Br0[2], Br1[2];
    const int nC = K >> 5;

    auto LOADG = [&](int c) {
        int kb = c << 5;
        #pragma unroll
        for (int i = 0; i < 4; i++) {
            int id = t + (i << 8);
            int m = id >> 3, k4 = (id & 7) << 2;
            int gm = row0 + m;
            Ar[i] = (gm < M) ? *(const float4*)&A[(ll)gm * Kfull + kb + k4]
                             : make_float4(0.f, 0.f, 0.f, 0.f);
        }
        #pragma unroll
        for (int i = 0; i < 2; i++) {
            int u = t + (i << 8);
            int kp = u >> 5, n2 = u & 31;
            const float* bp = &B[(ll)(kb + 2 * kp) * N + n0 + 2 * n2];
            Br0[i] = *(const float2*)bp;
            Br1[i] = *(const float2*)(bp + N);
        }
    };
    auto CONVST = [&]() {
        #pragma unroll
        for (int i = 0; i < 4; i++) {
            int id = t + (i << 8);
            int m = id >> 3, k4 = (id & 7) << 2;
            int c0, c1; pcol(k4 >> 1, c0, c1);
            u32 h0, l0, h1, l1;
            split2(Ar[i].x, Ar[i].y, h0, l0);
            split2(Ar[i].z, Ar[i].w, h1, l1);
            Ah[m * ASTR + c0] = h0; Ah[m * ASTR + c1] = h1;
            Al[m * ASTR + c0] = l0; Al[m * ASTR + c1] = l1;
        }
        #pragma unroll
        for (int i = 0; i < 2; i++) {
            int u = t + (i << 8);
            int kp = u >> 5, n2 = u & 31;
            int cc = pcol1(kp);
            u32 h0, l0, h1, l1;
            split2(Br0[i].x, Br1[i].x, h0, l0);
            split2(Br0[i].y, Br1[i].y, h1, l1);
            Bh[(2 * n2) * ASTR + cc] = h0;     Bl[(2 * n2) * ASTR + cc] = l0;
            Bh[(2 * n2 + 1) * ASTR + cc] = h1; Bl[(2 * n2 + 1) * ASTR + cc] = l1;
        }
    };

    LOADG(0); CONVST();
    __syncthreads();

    for (int c = 0; c < nC; c++) {
        const bool more = (c + 1 < nC);
        if (more) LOADG(c + 1);
        MMA_COMPUTE();
        __syncthreads();
        if (more) { CONVST(); __syncthreads(); }
    }

    float* Co = PARTIAL ? (C + (ll)zs * M * N) : C;
    #pragma unroll
    for (int mt = 0; mt < 2; mt++) {
        #pragma unroll
        for (int half = 0; half < 2; half++) {
            int gm = row0 + mw * 32 + mt * 16 + half * 8 + g;
            if (gm >= M) continue;
            #pragma unroll
            for (int nt = 0; nt < 4; nt++) {
                int gn = n0 + nw * 32 + nt * 8 + 2 * tg;
                float v0 = acc[mt][nt][half * 2 + 0];
                float v1 = acc[mt][nt][half * 2 + 1];
                if (!PARTIAL) {
                    v0 += bias[gn]; v1 += bias[gn + 1];
                    if (DOGELU) {
                        v0 = 0.5f * v0 * (1.f + erff(v0 * 0.70710678118654752440f));
                        v1 = 0.5f * v1 * (1.f + erff(v1 * 0.70710678118654752440f));
                    }
                    if (HASRES) {
                        v0 += res[(ll)gm * N + gn];
                        v1 += res[(ll)gm * N + gn + 1];
                    }
                }
                *(float2*)&Co[(ll)gm * N + gn] = make_float2(v0, v1);
            }
        }
    }
}

// ---------------- batched HMMA attention GEMM --------------------------------
// TRANSB=true : C = alpha * A @ B^T  (QK^T; blockIdx.x = N-tile; B rows < Bvalid)
// TRANSB=false: split-K PV: blockIdx.x = K-split; n0 = 0; CTA handles K tokens
//               [x*K, x*K+K); writes raw partials to C + x*partStride.
template<bool TRANSB>
__global__ __launch_bounds__(256) void tmma(
    const float* __restrict__ A, const float* __restrict__ B,
    float* __restrict__ C,
    int M, int K, int lda, int ldb, int ldc, int Hn,
    ll sAb, ll sAh_, ll sBb, ll sBh_, ll sCb, ll sCh_,
    float alpha, int Bvalid, ll partStride)
{
    __shared__ __align__(16) u32 Ah[128 * ASTR];
    __shared__ __align__(16) u32 Al[128 * ASTR];
    __shared__ __align__(16) u32 Bh[64 * ASTR];
    __shared__ __align__(16) u32 Bl[64 * ASTR];

    const int zb = blockIdx.z / Hn;
    const int zh = blockIdx.z % Hn;
    A += zb * sAb + zh * sAh_;
    B += zb * sBb + zh * sBh_;
    C += zb * sCb + zh * sCh_;

    const int t = threadIdx.x;
    const int lane = t & 31, wid = t >> 5;
    const int g = lane >> 2, tg = lane & 3;
    const int mw = wid & 3, nw = wid >> 2;
    const int row0 = blockIdx.y * 128;
    const int n0 = TRANSB ? blockIdx.x * 64 : 0;
    const int koff = TRANSB ? 0 : blockIdx.x * K;
    if (!TRANSB) C += (ll)blockIdx.x * partStride;

    float acc[2][4][4];
    #pragma unroll
    for (int i = 0; i < 2; i++)
        #pragma unroll
        for (int j = 0; j < 4; j++)
            #pragma unroll
            for (int k = 0; k < 4; k++) acc[i][j][k] = 0.f;

    float4 Ar[4];
    float4 Brt[2];
    float2 Br0[2], Br1[2];
    const int nC = K >> 5;

    auto LOADG = [&](int c) {
        int kb = koff + (c << 5);
        #pragma unroll
        for (int i = 0; i < 4; i++) {
            int id = t + (i << 8);
            int m = id >> 3, k4 = (id & 7) << 2;
            int gm = row0 + m;
            Ar[i] = (gm < M) ? *(const float4*)&A[(ll)gm * lda + kb + k4]
                             : make_float4(0.f, 0.f, 0.f, 0.f);
        }
        if (TRANSB) {
            #pragma unroll
            for (int i = 0; i < 2; i++) {
                int id = t + (i << 8);
                int n = id >> 3, k4 = (id & 7) << 2;
                int gn = n0 + n;
                Brt[i] = (gn < Bvalid) ? *(const float4*)&B[(ll)gn * ldb + kb + k4]
                                       : make_float4(0.f, 0.f, 0.f, 0.f);
            }
        } else {
            #pragma unroll
            for (int i = 0; i < 2; i++) {
                int u = t + (i << 8);
                int kp = u >> 5, n2 = u & 31;
                int gk = kb + 2 * kp;
                Br0[i] = (gk < Bvalid) ? *(const float2*)&B[(ll)gk * ldb + 2 * n2]
                                       : make_float2(0.f, 0.f);
                Br1[i] = (gk + 1 < Bvalid)
                       ? *(const float2*)&B[(ll)(gk + 1) * ldb + 2 * n2]
                       : make_float2(0.f, 0.f);
            }
        }
    };
    auto CONVST = [&]() {
        #pragma unroll
        for (int i = 0; i < 4; i++) {
            int id = t + (i << 8);
            int m = id >> 3, k4 = (id & 7) << 2;
            int c0, c1; pcol(k4 >> 1, c0, c1);
            u32 h0, l0, h1, l1;
            split2(Ar[i].x, Ar[i].y, h0, l0);
            split2(Ar[i].z, Ar[i].w, h1, l1);
            Ah[m * ASTR + c0] = h0; Ah[m * ASTR + c1] = h1;
            Al[m * ASTR + c0] = l0; Al[m * ASTR + c1] = l1;
        }
        if (TRANSB) {
            #pragma unroll
            for (int i = 0; i < 2; i++) {
                int id = t + (i << 8);
                int n = id >> 3, k4 = (id & 7) << 2;
                int c0, c1; pcol(k4 >> 1, c0, c1);
                u32 h0, l0, h1, l1;
                split2(Brt[i].x, Brt[i].y, h0, l0);
                split2(Brt[i].z, Brt[i].w, h1, l1);
                Bh[n * ASTR + c0] = h0; Bh[n * ASTR + c1] = h1;
                Bl[n * ASTR + c0] = l0; Bl[n * ASTR + c1] = l1;
            }
        } else {
            #pragma unroll
            for (int i = 0; i < 2; i++) {
                int u = t + (i << 8);
                int kp = u >> 5, n2 = u & 31;
                int cc = pcol1(kp);
                u32 h0, l0, h1, l1;
                split2(Br0[i].x, Br1[i].x, h0, l0);
                split2(Br0[i].y, Br1[i].y, h1, l1);
                Bh[(2 * n2) * ASTR + cc] = h0;     Bl[(2 * n2) * ASTR + cc] = l0;
                Bh[(2 * n2 + 1) * ASTR + cc] = h1; Bl[(2 * n2 + 1) * ASTR + cc] = l1;
            }
        }
    };

    LOADG(0); CONVST();
    __syncthreads();

    for (int c = 0; c < nC; c++) {
        const bool more = (c + 1 < nC);
        if (more) LOADG(c + 1);
        MMA_COMPUTE();
        __syncthreads();
        if (more) { CONVST(); __syncthreads(); }
    }

    #pragma unroll
    for (int mt = 0; mt < 2; mt++) {
        #pragma unroll
        for (int half = 0; half < 2; half++) {
            int gm = row0 + mw * 32 + mt * 16 + half * 8 + g;
            if (gm >= M) continue;
            float* crow = &C[(ll)gm * ldc];
            #pragma unroll
            for (int nt = 0; nt < 4; nt++) {
                int gn = n0 + nw * 32 + nt * 8 + 2 * tg;
                float v0 = acc[mt][nt][half * 2 + 0] * alpha;
                float v1 = acc[mt][nt][half * 2 + 1] * alpha;
                *(float2*)&crow[gn] = make_float2(v0, v1);
            }
        }
    }
}

// ---------------- split-K reducers (deterministic fixed order) ---------------
// ctx = p0 + p1 + p2 + p3
__global__ void red_ctx4(const float* __restrict__ p, float* __restrict__ o, int n)
{
    int i = blockIdx.x * 256 + threadIdx.x;
    if (i >= n) return;
    o[i] = ((p[i] + p[i + (ll)ROWS*DIM]) +
            (p[i + 2*(ll)ROWS*DIM] + p[i + 3*(ll)ROWS*DIM]));
}
// x += bias[col] + sum_{s<NS} p[s]
template<int NS>
__global__ void red_res(float* __restrict__ x, const float* __restrict__ p,
                        const float* __restrict__ bias, int n)
{
    int i = blockIdx.x * 256 + threadIdx.x;
    if (i >= n) return;
    int col = i - (i / DIM) * DIM;
    float s = bias[col];
    #pragma unroll
    for (int k = 0; k < NS; k++) s += p[i + (ll)k * ROWS * DIM];
    x[i] += s;
}

// ---------------- layernorm: one block per row, D=384 ------------------------
__global__ __launch_bounds__(128) void ln_k(
    const float* __restrict__ x, const float* __restrict__ g,
    const float* __restrict__ b, float* __restrict__ o)
{
    __shared__ float sh[4];
    ll row = blockIdx.x;
    const float* xr = x + row * DIM;
    float* orow = o + row * DIM;
    int t = threadIdx.x;
    float v0 = xr[t], v1 = xr[t + 128], v2 = xr[t + 256];
    float s = v0 + v1 + v2;
    #pragma unroll
    for (int ofs = 16; ofs; ofs >>= 1) s += __shfl_xor_sync(0xffffffffu, s, ofs);
    if ((t & 31) == 0) sh[t >> 5] = s;
    __syncthreads();
    float mean = (sh[0] + sh[1] + sh[2] + sh[3]) * (1.f / DIM);
    __syncthreads();
    float d0 = v0 - mean, d1 = v1 - mean, d2 = v2 - mean;
    float q = d0*d0 + d1*d1 + d2*d2;
    #pragma unroll
    for (int ofs = 16; ofs; ofs >>= 1) q += __shfl_xor_sync(0xffffffffu, q, ofs);
    if ((t & 31) == 0) sh[t >> 5] = q;
    __syncthreads();
    float var = (sh[0] + sh[1] + sh[2] + sh[3]) * (1.f / DIM);
    float r = rsqrtf(var + 1e-6f);
    orow[t]       = d0 * r * g[t]       + b[t];
    orow[t + 128] = d1 * r * g[t + 128] + b[t + 128];
    orow[t + 256] = d2 * r * g[t + 256] + b[t + 256];
}

// ---------------- softmax + mask (e>=0.1) + renorm ---------------------------
// max(e)=exp(0)=1 exactly, so p>=0.1*max(p) <=> e>=0.1.
__global__ __launch_bounds__(256) void softmax_k(
    const float* __restrict__ S, float* __restrict__ P, float* __restrict__ Pc)
{
    __shared__ float sh[8];
    ll row = blockIdx.x;
    const float* sr = S + row * SSTR;
    float* pr = P + row * SSTR;
    int t = threadIdx.x;

    float v[4];
    float mx = -3.4e38f;
    #pragma unroll
    for (int i = 0; i < 4; i++) {
        int j = t + i * 256;
        v[i] = (j < NTOK) ? sr[j] : -3.4e38f;
        mx = fmaxf(mx, v[i]);
    }
    #pragma unroll
    for (int o = 16; o; o >>= 1) mx = fmaxf(mx, __shfl_xor_sync(0xffffffffu, mx, o));
    if ((t & 31) == 0) sh[t >> 5] = mx;
    __syncthreads();
    float smax = sh[0];
    #pragma unroll
    for (int i = 1; i < 8; i++) smax = fmaxf(smax, sh[i]);
    __syncthreads();

    float sum = 0.f;
    #pragma unroll
    for (int i = 0; i < 4; i++) {
        int j = t + i * 256;
        float e = (j < NTOK) ? __expf(v[i] - smax) : 0.f;
        v[i] = (e >= 0.1f) ? e : 0.f;
        sum += v[i];
    }
    #pragma unroll
    for (int o = 16; o; o >>= 1) sum += __shfl_xor_sync(0xffffffffu, sum, o);
    if ((t & 31) == 0) sh[t >> 5] = sum;
    __syncthreads();
    float E = sh[0]+sh[1]+sh[2]+sh[3]+sh[4]+sh[5]+sh[6]+sh[7];
    float inv = 1.0f / E;

    float* pcrow = Pc ? (Pc + row * NTOK) : nullptr;
    #pragma unroll
    for (int i = 0; i < 4; i++) {
        int j = t + i * 256;
        float o = v[i] * inv;
        pr[j] = o;                        // pad cols (>=962) get 0
        if (Pc && j < NTOK) pcrow[j] = o;
    }
}

__global__ void copy_k(const float* __restrict__ a, float* __restrict__ o, int n)
{
    int i = blockIdx.x * 256 + threadIdx.x;
    if (i < n) o[i] = a[i];
}

// -----------------------------------------------------------------------------
extern "C" void kernel_launch(void* const* d_in, const int* in_sizes, int n_in,
                              void* d_out, int out_size)
{
    const float* x_in   = (const float*)d_in[0];
    const float* w_qkv  = (const float*)d_in[1];
    const float* b_qkv  = (const float*)d_in[2];
    const float* w_proj = (const float*)d_in[3];
    const float* b_proj = (const float*)d_in[4];
    const float* ln1g   = (const float*)d_in[5];
    const float* ln1b   = (const float*)d_in[6];
    const float* ln2g   = (const float*)d_in[7];
    const float* ln2b   = (const float*)d_in[8];
    const float* w_fc1  = (const float*)d_in[9];
    const float* b_fc1  = (const float*)d_in[10];
    const float* w_fc2  = (const float*)d_in[11];
    const float* b_fc2  = (const float*)d_in[12];
    const float* lnfg   = (const float*)d_in[13];
    const float* lnfb   = (const float*)d_in[14];

    float* out_feat = (float*)d_out;
    float* out_attn = out_feat + FEAT_SIZE;

    float *x_, *ln_, *qkv_, *attn_, *attnp_, *ctx_, *hid_, *part_;
    cudaGetSymbolAddress((void**)&x_,    g_x);
    cudaGetSymbolAddress((void**)&ln_,   g_ln);
    cudaGetSymbolAddress((void**)&qkv_,  g_qkv);
    cudaGetSymbolAddress((void**)&attn_, g_attn);
    cudaGetSymbolAddress((void**)&attnp_, g_attnp);
    cudaGetSymbolAddress((void**)&ctx_,  g_ctx);
    cudaGetSymbolAddress((void**)&hid_,  g_hid);
    cudaGetSymbolAddress((void**)&part_, g_part);

    copy_k<<<(FEAT_SIZE + 255) / 256, 256>>>(x_in, x_, FEAT_SIZE);

    const int mTc = (ROWS + 127) / 128;       // 16 dense M-tiles
    const int yAt = (NTOK + 127) / 128;       // 8 attention M-tiles
    const int nRed = (ROWS * DIM + 255) / 256;

    for (int l = 0; l < NLAYER; l++) {
        // LN1
        ln_k<<<ROWS, 128>>>(x_, ln1g + l * DIM, ln1b + l * DIM, ln_);

        // QKV = ln1 @ w_qkv[l] + b_qkv[l]   [1924x1152], K=384 (288 CTAs)
        mma_gemm<false, false, false><<<dim3(QKVD/64, mTc, 1), 256>>>(
            ln_, w_qkv + (ll)l*DIM*QKVD, b_qkv + l*QKVD, nullptr, qkv_,
            ROWS, QKVD, DIM, DIM);

        // scores = 0.125 * Q @ K^T  (padded ldc=1024; 1536 CTAs)
        tmma<true><<<dim3(SSTR/64, yAt, NZ), 256>>>(
            qkv_, qkv_ + DIM, attn_,
            NTOK, DH, QKVD, QKVD, SSTR, NH,
            (ll)NTOK*QKVD, DH, (ll)NTOK*QKVD, DH,
            (ll)NH*NTOK*SSTR, (ll)NTOK*SSTR,
            0.125f, NTOK, 0);

        // softmax + mask + renorm (compact copy for last layer)
        float* pc = (l == NLAYER - 1) ? out_attn : nullptr;
        softmax_k<<<NZ * NTOK, 256>>>(attn_, attnp_, pc);

        // ctx = P @ V  split-K x4 (K=256 each; 384 CTAs) -> partials -> reduce
        tmma<false><<<dim3(4, yAt, NZ), 256>>>(
            attnp_, qkv_ + 2*DIM, part_,
            NTOK, SSTR/4, SSTR, QKVD, DIM, NH,
            (ll)NH*NTOK*SSTR, (ll)NTOK*SSTR,
            (ll)NTOK*QKVD, DH,
            (ll)NTOK*DIM, DH,
            1.0f, NTOK, (ll)ROWS*DIM);
        red_ctx4<<<nRed, 256>>>(part_, ctx_, ROWS*DIM);

        // proj split-K x2 (K=192 each; 192 CTAs) -> x += bias + partials
        mma_gemm<false, false, true><<<dim3(DIM/64, mTc, 2), 256>>>(
            ctx_, w_proj + (ll)l*DIM*DIM, nullptr, nullptr, part_,
            ROWS, DIM, DIM/2, DIM);
        red_res<2><<<nRed, 256>>>(x_, part_, b_proj + l*DIM, ROWS*DIM);

        // LN2
        ln_k<<<ROWS, 128>>>(x_, ln2g + l * DIM, ln2b + l * DIM, ln_);

        // hid = gelu(ln2 @ w_fc1 + b)   [1924x1536], K=384 (384 CTAs)
        mma_gemm<true, false, false><<<dim3(HIDD/64, mTc, 1), 256>>>(
            ln_, w_fc1 + (ll)l*DIM*HIDD, b_fc1 + l*HIDD, nullptr, hid_,
            ROWS, HIDD, DIM, DIM);

        // fc2 split-K x4 (K=384 each; 384 CTAs) -> x += bias + partials
        mma_gemm<false, false, true><<<dim3(DIM/64, mTc, 4), 256>>>(
            hid_, w_fc2 + (ll)l*HIDD*DIM, nullptr, nullptr, part_,
            ROWS, DIM, HIDD/4, HIDD);
        red_res<4><<<nRed, 256>>>(x_, part_, b_fc2 + l*DIM, ROWS*DIM);
    }

    // final LN -> feats
    ln_k<<<ROWS, 128>>>(x_, lnfg, lnfb, out_feat);
}

// round 17
// speedup vs baseline: 1.2260x; 1.0078x over previous
#include <cuda_runtime.h>
#include <cuda_bf16.h>
#include <math.h>

#define BATCH  2
#define NTOK   962
#define DIM    384
#define NH     6
#define DH     64
#define NLAYER 12
#define ROWS   (BATCH*NTOK)          // 1924
#define QKVD   (3*DIM)               // 1152
#define HIDD   (4*DIM)               // 1536
#define FEAT_SIZE (ROWS*DIM)         // 738816
#define SSTR   1024                  // padded row stride for scores
#define NZ     (BATCH*NH)            // 12 attention batches

typedef unsigned long long u64;
typedef unsigned int u32;
typedef long long ll;

// ---------------- scratch (static device globals; no allocation) -------------
__device__ float g_x  [ROWS*DIM];
__device__ float g_ln [ROWS*DIM];
__device__ float g_qkv[ROWS*QKVD];
__device__ float g_attn[NZ*NTOK*SSTR];    // padded scores (47 MB)
__device__ float g_stat[NZ*NTOK*2];       // per-row (smax, inv)
__device__ float g_ctx[ROWS*DIM];
__device__ float g_hid[ROWS*HIDD];
__device__ float g_part[4*ROWS*DIM];      // split-K partials (11.8 MB)

// ---------------- bf16 split helpers -----------------------------------------
__device__ __forceinline__ void split2(float x, float y, u32& hi, u32& lo) {
    __nv_bfloat162 h = __floats2bfloat162_rn(x, y);
    float rx = x - __bfloat162float(h.x);
    float ry = y - __bfloat162float(h.y);
    __nv_bfloat162 l = __floats2bfloat162_rn(rx, ry);
    hi = *(u32*)&h; lo = *(u32*)&l;
}
__device__ __forceinline__ void mma16816(float c[4],
    u32 a0, u32 a1, u32 a2, u32 a3, u32 b0, u32 b1)
{
    asm volatile(
        "mma.sync.aligned.m16n8k16.row.col.f32.bf16.bf16.f32 "
        "{%0,%1,%2,%3}, {%4,%5,%6,%7}, {%8,%9}, {%0,%1,%2,%3};"
        : "+f"(c[0]), "+f"(c[1]), "+f"(c[2]), "+f"(c[3])
        : "r"(a0), "r"(a1), "r"(a2), "r"(a3), "r"(b0), "r"(b1));
}
#define ASTR 24
__device__ __forceinline__ int pcol1(int p) {
    return (p >> 3) * 8 + (((p & 7) & 3) * 2 + ((p & 7) >> 2));
}
__device__ __forceinline__ void pcol(int p0, int& c0, int& c1) {
    c0 = pcol1(p0); c1 = pcol1(p0 + 1);
}

#define MMA_COMPUTE()                                                           \
    _Pragma("unroll")                                                           \
    for (int s = 0; s < 2; s++) {                                               \
        const int co = s * 8 + 2 * tg;                                          \
        uint2 AH0[2], AH1[2], AL0[2], AL1[2];                                   \
        _Pragma("unroll")                                                       \
        for (int mt = 0; mt < 2; mt++) {                                        \
            int rb = (mw * 32 + mt * 16 + g) * ASTR + co;                       \
            AH0[mt] = *(const uint2*)&Ah[rb];                                   \
            AH1[mt] = *(const uint2*)&Ah[rb + 8 * ASTR];                        \
            AL0[mt] = *(const uint2*)&Al[rb];                                   \
            AL1[mt] = *(const uint2*)&Al[rb + 8 * ASTR];                        \
        }                                                                       \
        uint2 BHf[4], BLf[4];                                                   \
        _Pragma("unroll")                                                       \
        for (int nt = 0; nt < 4; nt++) {                                        \
            int rb = (nw * 32 + nt * 8 + g) * ASTR + co;                        \
            BHf[nt] = *(const uint2*)&Bh[rb];                                   \
            BLf[nt] = *(const uint2*)&Bl[rb];                                   \
        }                                                                       \
        _Pragma("unroll")                                                       \
        for (int mt = 0; mt < 2; mt++) {                                        \
            _Pragma("unroll")                                                   \
            for (int nt = 0; nt < 4; nt++) {                                    \
                mma16816(acc[mt][nt], AH0[mt].x, AH1[mt].x, AH0[mt].y, AH1[mt].y,\
                         BHf[nt].x, BHf[nt].y);                                 \
                mma16816(acc[mt][nt], AH0[mt].x, AH1[mt].x, AH0[mt].y, AH1[mt].y,\
                         BLf[nt].x, BLf[nt].y);                                 \
                mma16816(acc[mt][nt], AL0[mt].x, AL1[mt].x, AL0[mt].y, AL1[mt].y,\
                         BHf[nt].x, BHf[nt].y);                                 \
            }                                                                   \
        }                                                                       \
    }

// ---------------- dense HMMA GEMM (fp32 in, convert in-loop) -----------------
// PARTIAL=false: C = act(A@B + bias) [+res], gridDim.z must be 1.
// PARTIAL=true : split-K; CTA z handles K cols [z*K, z*K+K) of Kfull; writes
//                raw partial sums to C + z*M*N (bias/res applied by reducer).
template<bool DOGELU, bool HASRES, bool PARTIAL>
__global__ __launch_bounds__(256) void mma_gemm(
    const float* __restrict__ A, const float* __restrict__ B,
    const float* __restrict__ bias, const float* __restrict__ res,
    float* __restrict__ C, int M, int N, int K, int Kfull)
{
    __shared__ __align__(16) u32 Ah[128 * ASTR];
    __shared__ __align__(16) u32 Al[128 * ASTR];
    __shared__ __align__(16) u32 Bh[64 * ASTR];
    __shared__ __align__(16) u32 Bl[64 * ASTR];

    const int zs = blockIdx.z;
    A += zs * K;
    B += (ll)zs * K * N;

    const int t = threadIdx.x;
    const int lane = t & 31, wid = t >> 5;
    const int g = lane >> 2, tg = lane & 3;
    const int mw = wid & 3, nw = wid >> 2;
    const int row0 = blockIdx.y * 128;
    const int n0 = blockIdx.x * 64;

    float acc[2][4][4];
    #pragma unroll
    for (int i = 0; i < 2; i++)
        #pragma unroll
        for (int j = 0; j < 4; j++)
            #pragma unroll
            for (int k = 0; k < 4; k++) acc[i][j][k] = 0.f;

    float4 Ar[4];
    float2 Br0[2], Br1[2];
    const int nC = K >> 5;

    auto LOADG = [&](int c) {
        int kb = c << 5;
        #pragma unroll
        for (int i = 0; i < 4; i++) {
            int id = t + (i << 8);
            int m = id >> 3, k4 = (id & 7) << 2;
            int gm = row0 + m;
            Ar[i] = (gm < M) ? *(const float4*)&A[(ll)gm * Kfull + kb + k4]
                             : make_float4(0.f, 0.f, 0.f, 0.f);
        }
        #pragma unroll
        for (int i = 0; i < 2; i++) {
            int u = t + (i << 8);
            int kp = u >> 5, n2 = u & 31;
            const float* bp = &B[(ll)(kb + 2 * kp) * N + n0 + 2 * n2];
            Br0[i] = *(const float2*)bp;
            Br1[i] = *(const float2*)(bp + N);
        }
    };
    auto CONVST = [&]() {
        #pragma unroll
        for (int i = 0; i < 4; i++) {
            int id = t + (i << 8);
            int m = id >> 3, k4 = (id & 7) << 2;
            int c0, c1; pcol(k4 >> 1, c0, c1);
            u32 h0, l0, h1, l1;
            split2(Ar[i].x, Ar[i].y, h0, l0);
            split2(Ar[i].z, Ar[i].w, h1, l1);
            Ah[m * ASTR + c0] = h0; Ah[m * ASTR + c1] = h1;
            Al[m * ASTR + c0] = l0; Al[m * ASTR + c1] = l1;
        }
        #pragma unroll
        for (int i = 0; i < 2; i++) {
            int u = t + (i << 8);
            int kp = u >> 5, n2 = u & 31;
            int cc = pcol1(kp);
            u32 h0, l0, h1, l1;
            split2(Br0[i].x, Br1[i].x, h0, l0);
            split2(Br0[i].y, Br1[i].y, h1, l1);
            Bh[(2 * n2) * ASTR + cc] = h0;     Bl[(2 * n2) * ASTR + cc] = l0;
            Bh[(2 * n2 + 1) * ASTR + cc] = h1; Bl[(2 * n2 + 1) * ASTR + cc] = l1;
        }
    };

    LOADG(0); CONVST();
    __syncthreads();

    for (int c = 0; c < nC; c++) {
        const bool more = (c + 1 < nC);
        if (more) LOADG(c + 1);
        MMA_COMPUTE();
        __syncthreads();
        if (more) { CONVST(); __syncthreads(); }
    }

    float* Co = PARTIAL ? (C + (ll)zs * M * N) : C;
    #pragma unroll
    for (int mt = 0; mt < 2; mt++) {
        #pragma unroll
        for (int half = 0; half < 2; half++) {
            int gm = row0 + mw * 32 + mt * 16 + half * 8 + g;
            if (gm >= M) continue;
            #pragma unroll
            for (int nt = 0; nt < 4; nt++) {
                int gn = n0 + nw * 32 + nt * 8 + 2 * tg;
                float v0 = acc[mt][nt][half * 2 + 0];
                float v1 = acc[mt][nt][half * 2 + 1];
                if (!PARTIAL) {
                    v0 += bias[gn]; v1 += bias[gn + 1];
                    if (DOGELU) {
                        v0 = 0.5f * v0 * (1.f + erff(v0 * 0.70710678118654752440f));
                        v1 = 0.5f * v1 * (1.f + erff(v1 * 0.70710678118654752440f));
                    }
                    if (HASRES) {
                        v0 += res[(ll)gm * N + gn];
                        v1 += res[(ll)gm * N + gn + 1];
                    }
                }
                *(float2*)&Co[(ll)gm * N + gn] = make_float2(v0, v1);
            }
        }
    }
}

// ---------------- batched HMMA attention GEMM --------------------------------
// TRANSB=true : C = alpha * A @ B^T  (QK^T; blockIdx.x = N-tile; B rows < Bvalid)
// TRANSB=false: fused-softmax split-K PV: A = raw SCORES; per-row (smax, inv)
//               from Stats; A-tile conversion applies p = (e>=0.1 && col<NTOK)
//               ? e*inv : 0 before split-bf16.  blockIdx.x = K-split; writes raw
//               partials to C + x*partStride.
template<bool TRANSB>
__global__ __launch_bounds__(256) void tmma(
    const float* __restrict__ A, const float* __restrict__ B,
    const float* __restrict__ Stats,
    float* __restrict__ C,
    int M, int K, int lda, int ldb, int ldc, int Hn,
    ll sAb, ll sAh_, ll sBb, ll sBh_, ll sCb, ll sCh_,
    float alpha, int Bvalid, ll partStride)
{
    __shared__ __align__(16) u32 Ah[128 * ASTR];
    __shared__ __align__(16) u32 Al[128 * ASTR];
    __shared__ __align__(16) u32 Bh[64 * ASTR];
    __shared__ __align__(16) u32 Bl[64 * ASTR];
    __shared__ float sStat[256];

    const int zb = blockIdx.z / Hn;
    const int zh = blockIdx.z % Hn;
    A += zb * sAb + zh * sAh_;
    B += zb * sBb + zh * sBh_;
    C += zb * sCb + zh * sCh_;

    const int t = threadIdx.x;
    const int lane = t & 31, wid = t >> 5;
    const int g = lane >> 2, tg = lane & 3;
    const int mw = wid & 3, nw = wid >> 2;
    const int row0 = blockIdx.y * 128;
    const int n0 = TRANSB ? blockIdx.x * 64 : 0;
    const int koff = TRANSB ? 0 : blockIdx.x * K;
    if (!TRANSB) C += (ll)blockIdx.x * partStride;

    if (!TRANSB) {
        const float* st = Stats + (ll)blockIdx.z * NTOK * 2;
        if (t < 128) {
            int gm = row0 + t;
            float2 sv = (gm < M) ? *(const float2*)&st[2 * gm]
                                 : make_float2(0.f, 0.f);
            *(float2*)&sStat[2 * t] = sv;
        }
        __syncthreads();
    }

    float acc[2][4][4];
    #pragma unroll
    for (int i = 0; i < 2; i++)
        #pragma unroll
        for (int j = 0; j < 4; j++)
            #pragma unroll
            for (int k = 0; k < 4; k++) acc[i][j][k] = 0.f;

    float4 Ar[4];
    float4 Brt[2];
    float2 Br0[2], Br1[2];
    const int nC = K >> 5;

    auto LOADG = [&](int c) {
        int kb = koff + (c << 5);
        #pragma unroll
        for (int i = 0; i < 4; i++) {
            int id = t + (i << 8);
            int m = id >> 3, k4 = (id & 7) << 2;
            int gm = row0 + m;
            Ar[i] = (gm < M) ? *(const float4*)&A[(ll)gm * lda + kb + k4]
                             : make_float4(0.f, 0.f, 0.f, 0.f);
        }
        if (TRANSB) {
            #pragma unroll
            for (int i = 0; i < 2; i++) {
                int id = t + (i << 8);
                int n = id >> 3, k4 = (id & 7) << 2;
                int gn = n0 + n;
                Brt[i] = (gn < Bvalid) ? *(const float4*)&B[(ll)gn * ldb + kb + k4]
                                       : make_float4(0.f, 0.f, 0.f, 0.f);
            }
        } else {
            #pragma unroll
            for (int i = 0; i < 2; i++) {
                int u = t + (i << 8);
                int kp = u >> 5, n2 = u & 31;
                int gk = kb + 2 * kp;
                Br0[i] = (gk < Bvalid) ? *(const float2*)&B[(ll)gk * ldb + 2 * n2]
                                       : make_float2(0.f, 0.f);
                Br1[i] = (gk + 1 < Bvalid)
                       ? *(const float2*)&B[(ll)(gk + 1) * ldb + 2 * n2]
                       : make_float2(0.f, 0.f);
            }
        }
    };
    auto CONVST = [&](int cc) {
        #pragma unroll
        for (int i = 0; i < 4; i++) {
            int id = t + (i << 8);
            int m = id >> 3, k4 = (id & 7) << 2;
            float4 a = Ar[i];
            if (!TRANSB) {
                // fused softmax: p = (e >= 0.1 && col < NTOK) ? e*inv : 0
                int kb = koff + (cc << 5) + k4;
                float smax = sStat[2 * m], inv = sStat[2 * m + 1];
                float e;
                e = __expf(a.x - smax); a.x = (e >= 0.1f && kb + 0 < NTOK) ? e * inv : 0.f;
                e = __expf(a.y - smax); a.y = (e >= 0.1f && kb + 1 < NTOK) ? e * inv : 0.f;
                e = __expf(a.z - smax); a.z = (e >= 0.1f && kb + 2 < NTOK) ? e * inv : 0.f;
                e = __expf(a.w - smax); a.w = (e >= 0.1f && kb + 3 < NTOK) ? e * inv : 0.f;
            }
            int c0, c1; pcol(k4 >> 1, c0, c1);
            u32 h0, l0, h1, l1;
            split2(a.x, a.y, h0, l0);
            split2(a.z, a.w, h1, l1);
            Ah[m * ASTR + c0] = h0; Ah[m * ASTR + c1] = h1;
            Al[m * ASTR + c0] = l0; Al[m * ASTR + c1] = l1;
        }
        if (TRANSB) {
            #pragma unroll
            for (int i = 0; i < 2; i++) {
                int id = t + (i << 8);
                int n = id >> 3, k4 = (id & 7) << 2;
                int c0, c1; pcol(k4 >> 1, c0, c1);
                u32 h0, l0, h1, l1;
                split2(Brt[i].x, Brt[i].y, h0, l0);
                split2(Brt[i].z, Brt[i].w, h1, l1);
                Bh[n * ASTR + c0] = h0; Bh[n * ASTR + c1] = h1;
                Bl[n * ASTR + c0] = l0; Bl[n * ASTR + c1] = l1;
            }
        } else {
            #pragma unroll
            for (int i = 0; i < 2; i++) {
                int u = t + (i << 8);
                int kp = u >> 5, n2 = u & 31;
                int cc2 = pcol1(kp);
                u32 h0, l0, h1, l1;
                split2(Br0[i].x, Br1[i].x, h0, l0);
                split2(Br0[i].y, Br1[i].y, h1, l1);
                Bh[(2 * n2) * ASTR + cc2] = h0;     Bl[(2 * n2) * ASTR + cc2] = l0;
                Bh[(2 * n2 + 1) * ASTR + cc2] = h1; Bl[(2 * n2 + 1) * ASTR + cc2] = l1;
            }
        }
    };

    LOADG(0); CONVST(0);
    __syncthreads();

    for (int c = 0; c < nC; c++) {
        const bool more = (c + 1 < nC);
        if (more) LOADG(c + 1);
        MMA_COMPUTE();
        __syncthreads();
        if (more) { CONVST(c + 1); __syncthreads(); }
    }

    #pragma unroll
    for (int mt = 0; mt < 2; mt++) {
        #pragma unroll
        for (int half = 0; half < 2; half++) {
            int gm = row0 + mw * 32 + mt * 16 + half * 8 + g;
            if (gm >= M) continue;
            float* crow = &C[(ll)gm * ldc];
            #pragma unroll
            for (int nt = 0; nt < 4; nt++) {
                int gn = n0 + nw * 32 + nt * 8 + 2 * tg;
                float v0 = acc[mt][nt][half * 2 + 0] * alpha;
                float v1 = acc[mt][nt][half * 2 + 1] * alpha;
                *(float2*)&crow[gn] = make_float2(v0, v1);
            }
        }
    }
}

// ---------------- split-K reducer for ctx ------------------------------------
__global__ void red_ctx4(const float* __restrict__ p, float* __restrict__ o, int n)
{
    int i = blockIdx.x * 256 + threadIdx.x;
    if (i >= n) return;
    o[i] = ((p[i] + p[i + (ll)ROWS*DIM]) +
            (p[i + 2*(ll)ROWS*DIM] + p[i + 3*(ll)ROWS*DIM]));
}

// ---------------- fused residual-reduce + LayerNorm --------------------------
// One block per row (192 thr, float2/thread):
//   x[row] += bias + sum partials;  lnout[row] = LN(x[row]; g, b)
template<int NS>
__global__ __launch_bounds__(192) void redln_k(
    float* __restrict__ x, const float* __restrict__ p,
    const float* __restrict__ bias,
    const float* __restrict__ gw, const float* __restrict__ bw,
    float* __restrict__ lnout)
{
    __shared__ float sh[6];
    ll row = blockIdx.x;
    int t = threadIdx.x;
    ll i2 = row * 192 + t;

    float2 bb = ((const float2*)bias)[t];
    float2 xv = ((float2*)x)[i2];
    float sx = bb.x, sy = bb.y;
    #pragma unroll
    for (int k = 0; k < NS; k++) {
        float2 pv = ((const float2*)p)[i2 + (ll)k * (ROWS * DIM / 2)];
        sx += pv.x; sy += pv.y;
    }
    xv.x += sx; xv.y += sy;
    ((float2*)x)[i2] = xv;

    // LayerNorm over the row (384 elems, 6 warps)
    float s = xv.x + xv.y;
    #pragma unroll
    for (int o = 16; o; o >>= 1) s += __shfl_xor_sync(0xffffffffu, s, o);
    if ((t & 31) == 0) sh[t >> 5] = s;
    __syncthreads();
    float mean = (sh[0]+sh[1]+sh[2]+sh[3]+sh[4]+sh[5]) * (1.f / DIM);
    __syncthreads();
    float dx = xv.x - mean, dy = xv.y - mean;
    float q = dx * dx + dy * dy;
    #pragma unroll
    for (int o = 16; o; o >>= 1) q += __shfl_xor_sync(0xffffffffu, q, o);
    if ((t & 31) == 0) sh[t >> 5] = q;
    __syncthreads();
    float var = (sh[0]+sh[1]+sh[2]+sh[3]+sh[4]+sh[5]) * (1.f / DIM);
    float r = rsqrtf(var + 1e-6f);
    float2 gg = ((const float2*)gw)[t], be = ((const float2*)bw)[t];
    ((float2*)lnout)[i2] = make_float2(dx * r * gg.x + be.x,
                                       dy * r * gg.y + be.y);
}

// ---------------- plain layernorm (initial LN1) ------------------------------
__global__ __launch_bounds__(128) void ln_k(
    const float* __restrict__ x, const float* __restrict__ g,
    const float* __restrict__ b, float* __restrict__ o)
{
    __shared__ float sh[4];
    ll row = blockIdx.x;
    const float* xr = x + row * DIM;
    float* orow = o + row * DIM;
    int t = threadIdx.x;
    float v0 = xr[t], v1 = xr[t + 128], v2 = xr[t + 256];
    float s = v0 + v1 + v2;
    #pragma unroll
    for (int ofs = 16; ofs; ofs >>= 1) s += __shfl_xor_sync(0xffffffffu, s, ofs);
    if ((t & 31) == 0) sh[t >> 5] = s;
    __syncthreads();
    float mean = (sh[0] + sh[1] + sh[2] + sh[3]) * (1.f / DIM);
    __syncthreads();
    float d0 = v0 - mean, d1 = v1 - mean, d2 = v2 - mean;
    float q = d0*d0 + d1*d1 + d2*d2;
    #pragma unroll
    for (int ofs = 16; ofs; ofs >>= 1) q += __shfl_xor_sync(0xffffffffu, q, ofs);
    if ((t & 31) == 0) sh[t >> 5] = q;
    __syncthreads();
    float var = (sh[0] + sh[1] + sh[2] + sh[3]) * (1.f / DIM);
    float r = rsqrtf(var + 1e-6f);
    orow[t]       = d0 * r * g[t]       + b[t];
    orow[t + 128] = d1 * r * g[t + 128] + b[t + 128];
    orow[t + 256] = d2 * r * g[t + 256] + b[t + 256];
}

// ---------------- softmax stats: per-row (smax, inv) -------------------------
// max(e)=exp(0)=1 exactly, so p>=0.1*max(p) <=> e>=0.1.
__global__ __launch_bounds__(256) void softstat_k(
    const float* __restrict__ S, float* __restrict__ St)
{
    __shared__ float sh[8];
    ll row = blockIdx.x;
    const float* sr = S + row * SSTR;
    int t = threadIdx.x;

    float v[4];
    float mx = -3.4e38f;
    #pragma unroll
    for (int i = 0; i < 4; i++) {
        int j = t + i * 256;
        v[i] = (j < NTOK) ? sr[j] : -3.4e38f;
        mx = fmaxf(mx, v[i]);
    }
    #pragma unroll
    for (int o = 16; o; o >>= 1) mx = fmaxf(mx, __shfl_xor_sync(0xffffffffu, mx, o));
    if ((t & 31) == 0) sh[t >> 5] = mx;
    __syncthreads();
    float smax = sh[0];
    #pragma unroll
    for (int i = 1; i < 8; i++) smax = fmaxf(smax, sh[i]);
    __syncthreads();

    float sum = 0.f;
    #pragma unroll
    for (int i = 0; i < 4; i++) {
        int j = t + i * 256;
        float e = (j < NTOK) ? __expf(v[i] - smax) : 0.f;
        sum += (e >= 0.1f) ? e : 0.f;
    }
    #pragma unroll
    for (int o = 16; o; o >>= 1) sum += __shfl_xor_sync(0xffffffffu, sum, o);
    if ((t & 31) == 0) sh[t >> 5] = sum;
    __syncthreads();
    if (t == 0) {
        float E = sh[0]+sh[1]+sh[2]+sh[3]+sh[4]+sh[5]+sh[6]+sh[7];
        St[2 * row]     = smax;
        St[2 * row + 1] = 1.0f / E;
    }
}

// ---------------- compact masked softmax (last layer attn output) ------------
__global__ __launch_bounds__(256) void softmax_compact(
    const float* __restrict__ S, float* __restrict__ Pc)
{
    __shared__ float sh[8];
    ll row = blockIdx.x;
    const float* sr = S + row * SSTR;
    int t = threadIdx.x;

    float v[4];
    float mx = -3.4e38f;
    #pragma unroll
    for (int i = 0; i < 4; i++) {
        int j = t + i * 256;
        v[i] = (j < NTOK) ? sr[j] : -3.4e38f;
        mx = fmaxf(mx, v[i]);
    }
    #pragma unroll
    for (int o = 16; o; o >>= 1) mx = fmaxf(mx, __shfl_xor_sync(0xffffffffu, mx, o));
    if ((t & 31) == 0) sh[t >> 5] = mx;
    __syncthreads();
    float smax = sh[0];
    #pragma unroll
    for (int i = 1; i < 8; i++) smax = fmaxf(smax, sh[i]);
    __syncthreads();

    float sum = 0.f;
    #pragma unroll
    for (int i = 0; i < 4; i++) {
        int j = t + i * 256;
        float e = (j < NTOK) ? __expf(v[i] - smax) : 0.f;
        v[i] = (e >= 0.1f) ? e : 0.f;
        sum += v[i];
    }
    #pragma unroll
    for (int o = 16; o; o >>= 1) sum += __shfl_xor_sync(0xffffffffu, sum, o);
    if ((t & 31) == 0) sh[t >> 5] = sum;
    __syncthreads();
    float E = sh[0]+sh[1]+sh[2]+sh[3]+sh[4]+sh[5]+sh[6]+sh[7];
    float inv = 1.0f / E;

    float* pcrow = Pc + row * NTOK;
    #pragma unroll
    for (int i = 0; i < 4; i++) {
        int j = t + i * 256;
        if (j < NTOK) pcrow[j] = v[i] * inv;
    }
}

__global__ void copy_k(const float* __restrict__ a, float* __restrict__ o, int n)
{
    int i = blockIdx.x * 256 + threadIdx.x;
    if (i < n) o[i] = a[i];
}

// -----------------------------------------------------------------------------
extern "C" void kernel_launch(void* const* d_in, const int* in_sizes, int n_in,
                              void* d_out, int out_size)
{
    const float* x_in   = (const float*)d_in[0];
    const float* w_qkv  = (const float*)d_in[1];
    const float* b_qkv  = (const float*)d_in[2];
    const float* w_proj = (const float*)d_in[3];
    const float* b_proj = (const float*)d_in[4];
    const float* ln1g   = (const float*)d_in[5];
    const float* ln1b   = (const float*)d_in[6];
    const float* ln2g   = (const float*)d_in[7];
    const float* ln2b   = (const float*)d_in[8];
    const float* w_fc1  = (const float*)d_in[9];
    const float* b_fc1  = (const float*)d_in[10];
    const float* w_fc2  = (const float*)d_in[11];
    const float* b_fc2  = (const float*)d_in[12];
    const float* lnfg   = (const float*)d_in[13];
    const float* lnfb   = (const float*)d_in[14];

    float* out_feat = (float*)d_out;
    float* out_attn = out_feat + FEAT_SIZE;

    float *x_, *ln_, *qkv_, *attn_, *stat_, *ctx_, *hid_, *part_;
    cudaGetSymbolAddress((void**)&x_,    g_x);
    cudaGetSymbolAddress((void**)&ln_,   g_ln);
    cudaGetSymbolAddress((void**)&qkv_,  g_qkv);
    cudaGetSymbolAddress((void**)&attn_, g_attn);
    cudaGetSymbolAddress((void**)&stat_, g_stat);
    cudaGetSymbolAddress((void**)&ctx_,  g_ctx);
    cudaGetSymbolAddress((void**)&hid_,  g_hid);
    cudaGetSymbolAddress((void**)&part_, g_part);

    copy_k<<<(FEAT_SIZE + 255) / 256, 256>>>(x_in, x_, FEAT_SIZE);
    ln_k<<<ROWS, 128>>>(x_, ln1g, ln1b, ln_);

    const int mTc = (ROWS + 127) / 128;       // 16 dense M-tiles
    const int yAt = (NTOK + 127) / 128;       // 8 attention M-tiles
    const int nRed = (ROWS * DIM + 255) / 256;

    for (int l = 0; l < NLAYER; l++) {
        // QKV = ln1 @ w_qkv[l] + b_qkv[l]   [1924x1152], K=384
        mma_gemm<false, false, false><<<dim3(QKVD/64, mTc, 1), 256>>>(
            ln_, w_qkv + (ll)l*DIM*QKVD, b_qkv + l*QKVD, nullptr, qkv_,
            ROWS, QKVD, DIM, DIM);

        // scores = 0.125 * Q @ K^T  (padded ldc=1024; 1536 CTAs)
        tmma<true><<<dim3(SSTR/64, yAt, NZ), 256>>>(
            qkv_, qkv_ + DIM, nullptr, attn_,
            NTOK, DH, QKVD, QKVD, SSTR, NH,
            (ll)NTOK*QKVD, DH, (ll)NTOK*QKVD, DH,
            (ll)NH*NTOK*SSTR, (ll)NTOK*SSTR,
            0.125f, NTOK, 0);

        // per-row (smax, inv)
        softstat_k<<<NZ * NTOK, 256>>>(attn_, stat_);

        // last layer: compact masked attn output
        if (l == NLAYER - 1)
            softmax_compact<<<NZ * NTOK, 256>>>(attn_, out_attn);

        // ctx = softmax(scores) @ V, fused; split-K x4 -> partials -> reduce
        tmma<false><<<dim3(4, yAt, NZ), 256>>>(
            attn_, qkv_ + 2*DIM, stat_, part_,
            NTOK, SSTR/4, SSTR, QKVD, DIM, NH,
            (ll)NH*NTOK*SSTR, (ll)NTOK*SSTR,
            (ll)NTOK*QKVD, DH,
            (ll)NTOK*DIM, DH,
            1.0f, NTOK, (ll)ROWS*DIM);
        red_ctx4<<<nRed, 256>>>(part_, ctx_, ROWS*DIM);

        // proj split-K x2 -> x += bias + partials; ln_ = LN2(x)
        mma_gemm<false, false, true><<<dim3(DIM/64, mTc, 2), 256>>>(
            ctx_, w_proj + (ll)l*DIM*DIM, nullptr, nullptr, part_,
            ROWS, DIM, DIM/2, DIM);
        redln_k<2><<<ROWS, 192>>>(x_, part_, b_proj + l*DIM,
                                  ln2g + l*DIM, ln2b + l*DIM, ln_);

        // hid = gelu(ln2 @ w_fc1 + b)   [1924x1536], K=384
        mma_gemm<true, false, false><<<dim3(HIDD/64, mTc, 1), 256>>>(
            ln_, w_fc1 + (ll)l*DIM*HIDD, b_fc1 + l*HIDD, nullptr, hid_,
            ROWS, HIDD, DIM, DIM);

        // fc2 split-K x4 -> x += bias + partials; ln_ = LN1(next) or feats=LNf
        mma_gemm<false, false, true><<<dim3(DIM/64, mTc, 4), 256>>>(
            hid_, w_fc2 + (ll)l*HIDD*DIM, nullptr, nullptr, part_,
            ROWS, DIM, HIDD/4, HIDD);
        if (l < NLAYER - 1) {
            redln_k<4><<<ROWS, 192>>>(x_, part_, b_fc2 + l*DIM,
                                      ln1g + (l+1)*DIM, ln1b + (l+1)*DIM, ln_);
        } else {
            redln_k<4><<<ROWS, 192>>>(x_, part_, b_fc2 + l*DIM,
                                      lnfg, lnfb, out_feat);
        }
    }
}